// round 6
// baseline (speedup 1.0000x reference)
#include <cuda_runtime.h>
#include <cuda_bf16.h>
#include <cstdint>
#include <math.h>

typedef __nv_bfloat16 bf16;

#define NTOK 8192
#define DDIM 2048
#define KDIM 2048
#define SCALING_F (16.0f / 2048.0f)
#define EPS_F 1e-12f

// ---------------------------------------------------------------------------
// Static device scratch (allocation-free per harness rules)
// ---------------------------------------------------------------------------
__device__ bf16 g_x_hi [(size_t)NTOK * DDIM];
__device__ bf16 g_x_lo [(size_t)NTOK * DDIM];
__device__ bf16 g_lB_hi[(size_t)DDIM * DDIM];
__device__ bf16 g_lB_lo[(size_t)DDIM * DDIM];
__device__ bf16 g_lAT_hi[(size_t)DDIM * DDIM];   // lora_A transposed [i, r]
__device__ bf16 g_lAT_lo[(size_t)DDIM * DDIM];
__device__ bf16 g_dir_hi[(size_t)DDIM * DDIM];
__device__ bf16 g_dir_lo[(size_t)DDIM * DDIM];
__device__ bf16 g_P_hi [(size_t)DDIM * DDIM];    // P = lora_B @ lora_A  [o, i]
__device__ bf16 g_P_lo [(size_t)DDIM * DDIM];
__device__ bf16 g_QT_hi[(size_t)DDIM * DDIM];    // QT[oo,o] = cs[oo]*(dir @ P^T)
__device__ bf16 g_QT_lo[(size_t)DDIM * DDIM];
__device__ float g_cs[DDIM];

// ---------------------------------------------------------------------------
// PTX helpers — standard features only (sm_80+)
// ---------------------------------------------------------------------------
__device__ __forceinline__ uint32_t smem_u32(const void* p) {
    uint32_t a;
    asm("{ .reg .u64 t; cvta.to.shared.u64 t, %1; cvt.u32.u64 %0, t; }" : "=r"(a) : "l"(p));
    return a;
}

__device__ __forceinline__ void cp_async16(uint32_t dst, const void* src) {
    asm volatile("cp.async.cg.shared.global [%0], [%1], 16;" :: "r"(dst), "l"(src));
}
__device__ __forceinline__ void cp_commit() { asm volatile("cp.async.commit_group;" ::: "memory"); }
template <int N>
__device__ __forceinline__ void cp_wait() { asm volatile("cp.async.wait_group %0;" :: "n"(N) : "memory"); }

#define LDSM_X4(r0, r1, r2, r3, addr) \
    asm volatile("ldmatrix.sync.aligned.m8n8.x4.shared.b16 {%0,%1,%2,%3}, [%4];" \
        : "=r"(r0), "=r"(r1), "=r"(r2), "=r"(r3) : "r"(addr))

__device__ __forceinline__ void mma_bf16(float* c, const uint32_t* a, const uint32_t* b) {
    asm volatile(
        "mma.sync.aligned.m16n8k16.row.col.f32.bf16.bf16.f32 "
        "{%0,%1,%2,%3}, {%4,%5,%6,%7}, {%8,%9}, {%0,%1,%2,%3};"
        : "+f"(c[0]), "+f"(c[1]), "+f"(c[2]), "+f"(c[3])
        : "r"(a[0]), "r"(a[1]), "r"(a[2]), "r"(a[3]), "r"(b[0]), "r"(b[1]));
}

// ---------------------------------------------------------------------------
// Prep kernel 1: fused mag + colscale
// ---------------------------------------------------------------------------
__global__ void magcol_kernel(const float* __restrict__ magnitude,
                              const float* __restrict__ direction) {
    int o = blockIdx.x;
    const float* row = direction + (size_t)o * DDIM;
    float sm = 0.0f, sd = 0.0f;
    for (int i = threadIdx.x; i < DDIM; i += 256) {
        float a = magnitude[i];  sm += a * a;
        float b = row[i];        sd += b * b;
    }
    __shared__ float rm[256], rd[256];
    rm[threadIdx.x] = sm; rd[threadIdx.x] = sd;
    __syncthreads();
    for (int off = 128; off > 0; off >>= 1) {
        if (threadIdx.x < off) {
            rm[threadIdx.x] += rm[threadIdx.x + off];
            rd[threadIdx.x] += rd[threadIdx.x + off];
        }
        __syncthreads();
    }
    if (threadIdx.x == 0)
        g_cs[o] = sqrtf(rm[0]) * SCALING_F / fmaxf(sqrtf(rd[0]), EPS_F);
}

// ---------------------------------------------------------------------------
// Prep kernel 2: fused split of x, lora_B, direction (8 floats/thread)
// ---------------------------------------------------------------------------
__device__ __forceinline__ void split8(const float* __restrict__ in,
                                       bf16* __restrict__ hi, bf16* __restrict__ lo,
                                       int i) {
    float4 a = ((const float4*)in)[i * 2];
    float4 b = ((const float4*)in)[i * 2 + 1];
    float v[8] = {a.x, a.y, a.z, a.w, b.x, b.y, b.z, b.w};
    uint32_t hw[4], lw[4];
    #pragma unroll
    for (int q = 0; q < 4; q++) {
        bf16 h0 = __float2bfloat16(v[q * 2]);
        bf16 h1 = __float2bfloat16(v[q * 2 + 1]);
        __nv_bfloat162 hp; hp.x = h0; hp.y = h1;
        hw[q] = *(uint32_t*)&hp;
        __nv_bfloat162 lp;
        lp.x = __float2bfloat16(v[q * 2] - __bfloat162float(h0));
        lp.y = __float2bfloat16(v[q * 2 + 1] - __bfloat162float(h1));
        lw[q] = *(uint32_t*)&lp;
    }
    uint4 hv; hv.x = hw[0]; hv.y = hw[1]; hv.z = hw[2]; hv.w = hw[3];
    uint4 lv; lv.x = lw[0]; lv.y = lw[1]; lv.z = lw[2]; lv.w = lw[3];
    ((uint4*)hi)[i] = hv;
    ((uint4*)lo)[i] = lv;
}

#define NX8 ((NTOK * DDIM) / 8)
#define ND8 ((DDIM * DDIM) / 8)
#define BX  (NX8 / 256)
#define BD  (ND8 / 256)

__global__ void fused_split(const float* __restrict__ x,
                            const float* __restrict__ lB,
                            const float* __restrict__ dir,
                            bf16* __restrict__ xh, bf16* __restrict__ xl,
                            bf16* __restrict__ lBh, bf16* __restrict__ lBl,
                            bf16* __restrict__ dh,  bf16* __restrict__ dl) {
    int b = blockIdx.x;
    if (b < BX) {
        split8(x, xh, xl, b * 256 + threadIdx.x);
    } else if (b < BX + BD) {
        split8(lB, lBh, lBl, (b - BX) * 256 + threadIdx.x);
    } else {
        split8(dir, dh, dl, (b - BX - BD) * 256 + threadIdx.x);
    }
}

// fp32 [R, C] -> transposed split bf16 [C, R]
__global__ void transpose_split(const float* __restrict__ in, bf16* __restrict__ hi,
                                bf16* __restrict__ lo) {
    __shared__ float t[32][33];
    int bx = blockIdx.x * 32, by = blockIdx.y * 32;
    int tx = threadIdx.x, ty = threadIdx.y;  // 32 x 8
    #pragma unroll
    for (int j = 0; j < 32; j += 8)
        t[ty + j][tx] = in[(size_t)(by + ty + j) * DDIM + bx + tx];
    __syncthreads();
    #pragma unroll
    for (int j = 0; j < 32; j += 8) {
        float v = t[tx][ty + j];
        size_t o = (size_t)(bx + ty + j) * DDIM + by + tx;
        bf16 h = __float2bfloat16(v);
        hi[o] = h;
        lo[o] = __float2bfloat16(v - __bfloat162float(h));
    }
}

// ---------------------------------------------------------------------------
// Split-bf16 GEMM, 2 CTAs/SM version:
//   CTA tile 128x128, BK=32, 3-stage cp.async pipeline; stage = 32 KB
//   (Ah,Al,Bh,Bl tiles of 128 rows x 64 B). Total smem 96 KB -> occupancy 2.
//   Swizzle for 64B rows: phys col16 = col16 ^ ((row>>1)&3)  (conflict-free
//   for both 16B cp.async stores and ldmatrix reads).
//   Register discipline: B-hi frags consumed by hh+lh sweeps, then B-lo is
//   LDSM'd into the SAME registers for the hl sweep (peak frags = 40 regs).
// ---------------------------------------------------------------------------
template <int EPI>
__global__ __launch_bounds__(256, 2)
void gemm_split(const bf16* __restrict__ Ah_g, const bf16* __restrict__ Al_g,
                const bf16* __restrict__ Bh_g, const bf16* __restrict__ Bl_g,
                float* __restrict__ Cf, bf16* __restrict__ Chi, bf16* __restrict__ Clo,
                const float* __restrict__ rowscale)
{
    extern __shared__ __align__(128) char smem[];
    const uint32_t sb = smem_u32(smem);

    constexpr int K = KDIM, BK = 32, NC = K / BK, S = 3;
    constexpr uint32_t TILE = 128 * 64;      // 8 KB: 128 rows x 64 B
    constexpr uint32_t STAGE = 4 * TILE;     // 32 KB

    const int tid = threadIdx.x;
    const int m0 = blockIdx.y * 128;
    const int n0 = blockIdx.x * 128;
    const int ldc = gridDim.x * 128;
    const int wid = tid >> 5, lane = tid & 31;
    const int wm = (wid >> 2) * 64;   // warp row offset (0 / 64)
    const int wn = (wid & 3) * 32;    // warp col offset (0/32/64/96)

    // cp.async mapping: 8 x 16B per thread per stage (2 per tile)
    const int c16  = tid & 3;         // 16B column within 64B row
    const int lrow = tid >> 2;        // 0..63
    const bf16* gp0 = Ah_g + (size_t)m0 * K;
    const bf16* gp1 = Al_g + (size_t)m0 * K;
    const bf16* gp2 = Bh_g + (size_t)n0 * K;
    const bf16* gp3 = Bl_g + (size_t)n0 * K;

    auto load_stage = [&](int slot, int c) {
        const uint32_t base = sb + (uint32_t)slot * STAGE;
        const int k0 = c * BK + c16 * 8;
        #pragma unroll
        for (int t = 0; t < 4; t++) {
            const bf16* bp = (t == 0) ? gp0 : (t == 1) ? gp1 : (t == 2) ? gp2 : gp3;
            #pragma unroll
            for (int j = 0; j < 2; j++) {
                const int row = lrow + 64 * j;
                const uint32_t pc = (uint32_t)(c16 ^ ((row >> 1) & 3));
                uint32_t dst = base + (uint32_t)t * TILE + (uint32_t)row * 64 + pc * 16;
                cp_async16(dst, bp + (size_t)row * K + k0);
            }
        }
        cp_commit();
    };

    float acc[4][4][4];
    #pragma unroll
    for (int a = 0; a < 4; a++)
        #pragma unroll
        for (int b = 0; b < 4; b++)
            #pragma unroll
            for (int q = 0; q < 4; q++) acc[a][b][q] = 0.0f;

    load_stage(0, 0);
    load_stage(1, 1);

    // ldmatrix lane components
    const int a_row_l = lane & 15;                        // row within 16-row tile
    const int a_c16_l = lane >> 4;                        // 16B half of k16 (0/1)
    const int b_n_l   = (lane & 7) + ((lane >> 4) << 3);  // row within 16-col group
    const int b_c16_l = (lane >> 3) & 1;

    for (int c = 0; c < NC; c++) {
        if (c + 1 < NC) cp_wait<1>(); else cp_wait<0>();
        __syncthreads();
        if (c + 2 < NC) load_stage((c + 2) % S, c + 2);

        const uint32_t stg = sb + (uint32_t)(c % S) * STAGE;
        const uint32_t As_h = stg, As_l = stg + TILE;
        const uint32_t Bs_h = stg + 2 * TILE, Bs_l = stg + 3 * TILE;

        #pragma unroll
        for (int s = 0; s < 2; s++) {            // 2 k16 steps per 32-chunk
            uint32_t ah[4][4], al[4][4], bb[4][2];
            // A fragments (hi + lo)
            #pragma unroll
            for (int mi = 0; mi < 4; mi++) {
                const int row = wm + mi * 16 + a_row_l;
                const uint32_t pc = (uint32_t)((s * 2 + a_c16_l) ^ ((row >> 1) & 3));
                const uint32_t off = (uint32_t)row * 64 + pc * 16;
                LDSM_X4(ah[mi][0], ah[mi][1], ah[mi][2], ah[mi][3], As_h + off);
                LDSM_X4(al[mi][0], al[mi][1], al[mi][2], al[mi][3], As_l + off);
            }
            // B-hi fragments
            #pragma unroll
            for (int nj2 = 0; nj2 < 2; nj2++) {
                const int nr = wn + nj2 * 16 + b_n_l;
                const uint32_t pc = (uint32_t)((s * 2 + b_c16_l) ^ ((nr >> 1) & 3));
                const uint32_t off = (uint32_t)nr * 64 + pc * 16;
                LDSM_X4(bb[2*nj2][0], bb[2*nj2][1], bb[2*nj2+1][0], bb[2*nj2+1][1],
                        Bs_h + off);
            }
            // hh sweep
            #pragma unroll
            for (int mi = 0; mi < 4; mi++)
                #pragma unroll
                for (int nj = 0; nj < 4; nj++)
                    mma_bf16(acc[mi][nj], ah[mi], bb[nj]);
            // lh sweep (Al * Bh)
            #pragma unroll
            for (int mi = 0; mi < 4; mi++)
                #pragma unroll
                for (int nj = 0; nj < 4; nj++)
                    mma_bf16(acc[mi][nj], al[mi], bb[nj]);
            // reload bb <- B-lo (reuses registers), hl sweep (Ah * Bl)
            #pragma unroll
            for (int nj2 = 0; nj2 < 2; nj2++) {
                const int nr = wn + nj2 * 16 + b_n_l;
                const uint32_t pc = (uint32_t)((s * 2 + b_c16_l) ^ ((nr >> 1) & 3));
                const uint32_t off = (uint32_t)nr * 64 + pc * 16;
                LDSM_X4(bb[2*nj2][0], bb[2*nj2][1], bb[2*nj2+1][0], bb[2*nj2+1][1],
                        Bs_l + off);
            }
            #pragma unroll
            for (int mi = 0; mi < 4; mi++)
                #pragma unroll
                for (int nj = 0; nj < 4; nj++)
                    mma_bf16(acc[mi][nj], ah[mi], bb[nj]);
        }
    }

    // ---------------- epilogue ----------------
    const int g  = lane >> 2;
    const int t4 = lane & 3;
    #pragma unroll
    for (int mi = 0; mi < 4; mi++) {
        const int r0 = m0 + wm + mi * 16 + g;
        const int r1 = r0 + 8;
        float rs0 = 1.0f, rs1 = 1.0f;
        if (EPI == 2) { rs0 = rowscale[r0]; rs1 = rowscale[r1]; }
        #pragma unroll
        for (int nj = 0; nj < 4; nj++) {
            const int col = n0 + wn + nj * 8 + t4 * 2;
            float c0 = acc[mi][nj][0], c1 = acc[mi][nj][1];
            float c2 = acc[mi][nj][2], c3 = acc[mi][nj][3];
            if (EPI == 0) {
                float2 v0; v0.x = c0; v0.y = c1;
                float2 v1; v1.x = c2; v1.y = c3;
                *(float2*)(Cf + (size_t)r0 * ldc + col) = v0;
                *(float2*)(Cf + (size_t)r1 * ldc + col) = v1;
            } else {
                c0 *= rs0; c1 *= rs0; c2 *= rs1; c3 *= rs1;
                bf16 h0 = __float2bfloat16(c0), h1 = __float2bfloat16(c1);
                bf16 h2 = __float2bfloat16(c2), h3 = __float2bfloat16(c3);
                __nv_bfloat162 hp0; hp0.x = h0; hp0.y = h1;
                __nv_bfloat162 hp1; hp1.x = h2; hp1.y = h3;
                __nv_bfloat162 lp0, lp1;
                lp0.x = __float2bfloat16(c0 - __bfloat162float(h0));
                lp0.y = __float2bfloat16(c1 - __bfloat162float(h1));
                lp1.x = __float2bfloat16(c2 - __bfloat162float(h2));
                lp1.y = __float2bfloat16(c3 - __bfloat162float(h3));
                *(__nv_bfloat162*)(Chi + (size_t)r0 * ldc + col) = hp0;
                *(__nv_bfloat162*)(Chi + (size_t)r1 * ldc + col) = hp1;
                *(__nv_bfloat162*)(Clo + (size_t)r0 * ldc + col) = lp0;
                *(__nv_bfloat162*)(Clo + (size_t)r1 * ldc + col) = lp1;
            }
        }
    }
}

// ---------------------------------------------------------------------------
// Launch
// ---------------------------------------------------------------------------
static constexpr int GEMM_SMEM = 3 * 4 * 128 * 64;  // 98304 bytes

extern "C" void kernel_launch(void* const* d_in, const int* in_sizes, int n_in,
                              void* d_out, int out_size) {
    const float* x         = (const float*)d_in[0];  // [N, D]
    const float* lora_A    = (const float*)d_in[1];  // [r, i]
    const float* lora_B    = (const float*)d_in[2];  // [o, r]
    const float* magnitude = (const float*)d_in[3];  // [D]
    const float* direction = (const float*)d_in[4];  // [oo, i]
    float* out = (float*)d_out;                      // [N, D]

    bf16 *x_hi, *x_lo, *lB_hi, *lB_lo, *lAT_hi, *lAT_lo, *dir_hi, *dir_lo;
    bf16 *P_hi, *P_lo, *QT_hi, *QT_lo;
    float* cs;
    cudaGetSymbolAddress((void**)&x_hi, g_x_hi);   cudaGetSymbolAddress((void**)&x_lo, g_x_lo);
    cudaGetSymbolAddress((void**)&lB_hi, g_lB_hi); cudaGetSymbolAddress((void**)&lB_lo, g_lB_lo);
    cudaGetSymbolAddress((void**)&lAT_hi, g_lAT_hi); cudaGetSymbolAddress((void**)&lAT_lo, g_lAT_lo);
    cudaGetSymbolAddress((void**)&dir_hi, g_dir_hi); cudaGetSymbolAddress((void**)&dir_lo, g_dir_lo);
    cudaGetSymbolAddress((void**)&P_hi, g_P_hi);   cudaGetSymbolAddress((void**)&P_lo, g_P_lo);
    cudaGetSymbolAddress((void**)&QT_hi, g_QT_hi); cudaGetSymbolAddress((void**)&QT_lo, g_QT_lo);
    cudaGetSymbolAddress((void**)&cs, g_cs);

    cudaFuncSetAttribute(gemm_split<0>, cudaFuncAttributeMaxDynamicSharedMemorySize, GEMM_SMEM);
    cudaFuncSetAttribute(gemm_split<1>, cudaFuncAttributeMaxDynamicSharedMemorySize, GEMM_SMEM);
    cudaFuncSetAttribute(gemm_split<2>, cudaFuncAttributeMaxDynamicSharedMemorySize, GEMM_SMEM);

    // 1: fused split of x, lora_B, direction
    fused_split<<<BX + 2 * BD, 256>>>(x, lora_B, direction,
                                      x_hi, x_lo, lB_hi, lB_lo, dir_hi, dir_lo);
    // 2: transpose+split lora_A
    dim3 tgrid(DDIM / 32, DDIM / 32), tblk(32, 8);
    transpose_split<<<tgrid, tblk>>>(lora_A, lAT_hi, lAT_lo);
    // 3: fused mag + colscale
    magcol_kernel<<<DDIM, 256>>>(magnitude, direction);

    // 4: P[o,i] = sum_r lora_B[o,r] * lora_A_T[i,r]   (split epilogue)
    dim3 gs(DDIM / 128, DDIM / 128);
    gemm_split<1><<<gs, 256, GEMM_SMEM>>>(lB_hi, lB_lo, lAT_hi, lAT_lo,
                                          nullptr, P_hi, P_lo, nullptr);
    // 5: QT[oo,o] = cs[oo] * sum_i direction[oo,i] * P[o,i]  (split + rowscale)
    gemm_split<2><<<gs, 256, GEMM_SMEM>>>(dir_hi, dir_lo, P_hi, P_lo,
                                          nullptr, QT_hi, QT_lo, cs);
    // 6: out[n,oo] = sum_o x[n,o] * QT[oo,o]   (fp32 epilogue)
    dim3 gb(DDIM / 128, NTOK / 128);
    gemm_split<0><<<gb, 256, GEMM_SMEM>>>(x_hi, x_lo, QT_hi, QT_lo,
                                          out, nullptr, nullptr, nullptr);
}

// round 7
// speedup vs baseline: 1.0354x; 1.0354x over previous
#include <cuda_runtime.h>
#include <cuda_bf16.h>
#include <cstdint>
#include <math.h>

typedef __nv_bfloat16 bf16;

#define NTOK 8192
#define DDIM 2048
#define KDIM 2048
#define SCALING_F (16.0f / 2048.0f)
#define EPS_F 1e-12f

// ---------------------------------------------------------------------------
// Static device scratch
// ---------------------------------------------------------------------------
__device__ bf16 g_x_hi [(size_t)NTOK * DDIM];
__device__ bf16 g_x_lo [(size_t)NTOK * DDIM];
__device__ bf16 g_lB_hi[(size_t)DDIM * DDIM];
__device__ bf16 g_lB_lo[(size_t)DDIM * DDIM];
__device__ bf16 g_lAT_hi[(size_t)DDIM * DDIM];
__device__ bf16 g_lAT_lo[(size_t)DDIM * DDIM];
__device__ bf16 g_dir_hi[(size_t)DDIM * DDIM];
__device__ bf16 g_dir_lo[(size_t)DDIM * DDIM];
__device__ bf16 g_P_hi [(size_t)DDIM * DDIM];
__device__ bf16 g_P_lo [(size_t)DDIM * DDIM];
__device__ bf16 g_QT_hi[(size_t)DDIM * DDIM];
__device__ bf16 g_QT_lo[(size_t)DDIM * DDIM];
__device__ float g_cs[DDIM];

// ---------------------------------------------------------------------------
// PTX helpers — standard features only (sm_80+)
// ---------------------------------------------------------------------------
__device__ __forceinline__ uint32_t smem_u32(const void* p) {
    uint32_t a;
    asm("{ .reg .u64 t; cvta.to.shared.u64 t, %1; cvt.u32.u64 %0, t; }" : "=r"(a) : "l"(p));
    return a;
}

__device__ __forceinline__ void cp_async16(uint32_t dst, const void* src) {
    asm volatile("cp.async.cg.shared.global [%0], [%1], 16;" :: "r"(dst), "l"(src));
}
__device__ __forceinline__ void cp_commit() { asm volatile("cp.async.commit_group;" ::: "memory"); }
template <int N>
__device__ __forceinline__ void cp_wait() { asm volatile("cp.async.wait_group %0;" :: "n"(N) : "memory"); }

#define LDSM_X4(r0, r1, r2, r3, addr) \
    asm volatile("ldmatrix.sync.aligned.m8n8.x4.shared.b16 {%0,%1,%2,%3}, [%4];" \
        : "=r"(r0), "=r"(r1), "=r"(r2), "=r"(r3) : "r"(addr))

__device__ __forceinline__ void mma_bf16(float* c, const uint32_t* a, const uint32_t* b) {
    asm volatile(
        "mma.sync.aligned.m16n8k16.row.col.f32.bf16.bf16.f32 "
        "{%0,%1,%2,%3}, {%4,%5,%6,%7}, {%8,%9}, {%0,%1,%2,%3};"
        : "+f"(c[0]), "+f"(c[1]), "+f"(c[2]), "+f"(c[3])
        : "r"(a[0]), "r"(a[1]), "r"(a[2]), "r"(a[3]), "r"(b[0]), "r"(b[1]));
}

// ---------------------------------------------------------------------------
// Prep kernels (unchanged — measured fast enough)
// ---------------------------------------------------------------------------
__global__ void magcol_kernel(const float* __restrict__ magnitude,
                              const float* __restrict__ direction) {
    int o = blockIdx.x;
    const float* row = direction + (size_t)o * DDIM;
    float sm = 0.0f, sd = 0.0f;
    for (int i = threadIdx.x; i < DDIM; i += 256) {
        float a = magnitude[i];  sm += a * a;
        float b = row[i];        sd += b * b;
    }
    __shared__ float rm[256], rd[256];
    rm[threadIdx.x] = sm; rd[threadIdx.x] = sd;
    __syncthreads();
    for (int off = 128; off > 0; off >>= 1) {
        if (threadIdx.x < off) {
            rm[threadIdx.x] += rm[threadIdx.x + off];
            rd[threadIdx.x] += rd[threadIdx.x + off];
        }
        __syncthreads();
    }
    if (threadIdx.x == 0)
        g_cs[o] = sqrtf(rm[0]) * SCALING_F / fmaxf(sqrtf(rd[0]), EPS_F);
}

__device__ __forceinline__ void split8(const float* __restrict__ in,
                                       bf16* __restrict__ hi, bf16* __restrict__ lo,
                                       int i) {
    float4 a = ((const float4*)in)[i * 2];
    float4 b = ((const float4*)in)[i * 2 + 1];
    float v[8] = {a.x, a.y, a.z, a.w, b.x, b.y, b.z, b.w};
    uint32_t hw[4], lw[4];
    #pragma unroll
    for (int q = 0; q < 4; q++) {
        bf16 h0 = __float2bfloat16(v[q * 2]);
        bf16 h1 = __float2bfloat16(v[q * 2 + 1]);
        __nv_bfloat162 hp; hp.x = h0; hp.y = h1;
        hw[q] = *(uint32_t*)&hp;
        __nv_bfloat162 lp;
        lp.x = __float2bfloat16(v[q * 2] - __bfloat162float(h0));
        lp.y = __float2bfloat16(v[q * 2 + 1] - __bfloat162float(h1));
        lw[q] = *(uint32_t*)&lp;
    }
    uint4 hv; hv.x = hw[0]; hv.y = hw[1]; hv.z = hw[2]; hv.w = hw[3];
    uint4 lv; lv.x = lw[0]; lv.y = lw[1]; lv.z = lw[2]; lv.w = lw[3];
    ((uint4*)hi)[i] = hv;
    ((uint4*)lo)[i] = lv;
}

#define NX8 ((NTOK * DDIM) / 8)
#define ND8 ((DDIM * DDIM) / 8)
#define BX  (NX8 / 256)
#define BD  (ND8 / 256)

__global__ void fused_split(const float* __restrict__ x,
                            const float* __restrict__ lB,
                            const float* __restrict__ dir,
                            bf16* __restrict__ xh, bf16* __restrict__ xl,
                            bf16* __restrict__ lBh, bf16* __restrict__ lBl,
                            bf16* __restrict__ dh,  bf16* __restrict__ dl) {
    int b = blockIdx.x;
    if (b < BX) {
        split8(x, xh, xl, b * 256 + threadIdx.x);
    } else if (b < BX + BD) {
        split8(lB, lBh, lBl, (b - BX) * 256 + threadIdx.x);
    } else {
        split8(dir, dh, dl, (b - BX - BD) * 256 + threadIdx.x);
    }
}

__global__ void transpose_split(const float* __restrict__ in, bf16* __restrict__ hi,
                                bf16* __restrict__ lo) {
    __shared__ float t[32][33];
    int bx = blockIdx.x * 32, by = blockIdx.y * 32;
    int tx = threadIdx.x, ty = threadIdx.y;  // 32 x 8
    #pragma unroll
    for (int j = 0; j < 32; j += 8)
        t[ty + j][tx] = in[(size_t)(by + ty + j) * DDIM + bx + tx];
    __syncthreads();
    #pragma unroll
    for (int j = 0; j < 32; j += 8) {
        float v = t[tx][ty + j];
        size_t o = (size_t)(bx + ty + j) * DDIM + by + tx;
        bf16 h = __float2bfloat16(v);
        hi[o] = h;
        lo[o] = __float2bfloat16(v - __bfloat162float(h));
    }
}

// ---------------------------------------------------------------------------
// PERSISTENT split-bf16 GEMM: C[tilesM*128, tilesN*128] = A * B^T, K = 2048.
// grid = #SMs; each CTA walks tiles with stride gridDim.x. The 3-stage
// cp.async pipeline continues ACROSS tiles: during the last 2 chunks of tile
// t, chunks 0-1 of tile t+grid are prefetched; the epilogue overlaps them.
// BK=64, smem 196KB (occ 1), frag double-buffering, SW128 XOR swizzle.
// ---------------------------------------------------------------------------
template <int EPI>
__global__ __launch_bounds__(256, 1)
void gemm_split(const bf16* __restrict__ Ah_g, const bf16* __restrict__ Al_g,
                const bf16* __restrict__ Bh_g, const bf16* __restrict__ Bl_g,
                float* __restrict__ Cf, bf16* __restrict__ Chi, bf16* __restrict__ Clo,
                const float* __restrict__ rowscale, int tilesM, int tilesN)
{
    extern __shared__ __align__(128) char smem[];
    const uint32_t sb = smem_u32(smem);

    constexpr int K = KDIM, BK = 64, NC = K / BK, S = 3;
    constexpr uint32_t TILE = 128 * 128;
    constexpr uint32_t STAGE = 4 * TILE;

    const int T = tilesM * tilesN;
    const int ldc = tilesN * 128;
    const int tid = threadIdx.x;
    const int wid = tid >> 5, lane = tid & 31;
    const int wm = (wid >> 2) * 64;
    const int wn = (wid & 3) * 32;

    const int lrow = tid >> 3;
    const int lg   = tid & 7;

    // ldmatrix lane components
    const int a_row_l = lane & 15;
    const int a_kb_l  = (lane >> 4) * 16;
    const int b_n_l   = (lane & 7) + ((lane >> 4) << 3);
    const int b_kb_l  = ((lane >> 3) & 1) * 16;

    int tile = blockIdx.x;
    if (tile >= T) return;
    int tm = tile / tilesN, tn = tile - tm * tilesN;
    const bf16* ca_h = Ah_g + (size_t)tm * 128 * K;
    const bf16* ca_l = Al_g + (size_t)tm * 128 * K;
    const bf16* cb_h = Bh_g + (size_t)tn * 128 * K;
    const bf16* cb_l = Bl_g + (size_t)tn * 128 * K;

    auto load_stage = [&](int slot, const bf16* p0, const bf16* p1,
                          const bf16* p2, const bf16* p3, int k0) {
        const uint32_t base = sb + (uint32_t)slot * STAGE;
        const int ks = k0 + lg * 8;
        #pragma unroll
        for (int t = 0; t < 4; t++) {
            const bf16* bp = (t == 0) ? p0 : (t == 1) ? p1 : (t == 2) ? p2 : p3;
            #pragma unroll
            for (int j = 0; j < 4; j++) {
                const int row = lrow + 32 * j;
                uint32_t off = (uint32_t)row * 128 + (uint32_t)lg * 16;
                off ^= ((uint32_t)row & 7) << 4;
                cp_async16(base + (uint32_t)t * TILE + off, bp + (size_t)row * K + ks);
            }
        }
        cp_commit();
    };

    // prologue: first tile, chunks 0 and 1 into slots 0 and 1
    load_stage(0, ca_h, ca_l, cb_h, cb_l, 0);
    load_stage(1, ca_h, ca_l, cb_h, cb_l, BK);

    int scur = 0, sld = 2;   // consume slot / next load slot (rotate mod S forever)

    uint32_t ah[2][4][4], al[2][4][4], bh[2][4][2], bl[2][4][2];

    while (true) {
        const int ntile = tile + gridDim.x;
        const bool have_next = ntile < T;
        const bf16 *na_h = ca_h, *na_l = ca_l, *nb_h = cb_h, *nb_l = cb_l;
        int nm = tm, nn = tn;
        if (have_next) {
            nm = ntile / tilesN; nn = ntile - nm * tilesN;
            na_h = Ah_g + (size_t)nm * 128 * K;
            na_l = Al_g + (size_t)nm * 128 * K;
            nb_h = Bh_g + (size_t)nn * 128 * K;
            nb_l = Bl_g + (size_t)nn * 128 * K;
        }

        float acc[4][4][4];
        #pragma unroll
        for (int a = 0; a < 4; a++)
            #pragma unroll
            for (int b = 0; b < 4; b++)
                #pragma unroll
                for (int q = 0; q < 4; q++) acc[a][b][q] = 0.0f;

        for (int c = 0; c < NC; c++) {
            if (c == NC - 1 && !have_next) cp_wait<0>(); else cp_wait<1>();
            __syncthreads();

            if (c + 2 < NC)
                load_stage(sld, ca_h, ca_l, cb_h, cb_l, (c + 2) * BK);
            else if (have_next)
                load_stage(sld, na_h, na_l, nb_h, nb_l, (c + 2 - NC) * BK);

            const uint32_t stg = sb + (uint32_t)scur * STAGE;
            const uint32_t As_h = stg, As_l = stg + TILE;
            const uint32_t Bs_h = stg + 2 * TILE, Bs_l = stg + 3 * TILE;

            auto load_frags = [&](int buf, int s) {
                const int kb = s * 32;
                #pragma unroll
                for (int mi = 0; mi < 4; mi++) {
                    const int row = wm + mi * 16 + a_row_l;
                    const uint32_t off = (uint32_t)row * 128
                        + (((uint32_t)(kb + a_kb_l)) ^ (((uint32_t)row & 7) << 4));
                    LDSM_X4(ah[buf][mi][0], ah[buf][mi][1], ah[buf][mi][2], ah[buf][mi][3], As_h + off);
                    LDSM_X4(al[buf][mi][0], al[buf][mi][1], al[buf][mi][2], al[buf][mi][3], As_l + off);
                }
                #pragma unroll
                for (int nj2 = 0; nj2 < 2; nj2++) {
                    const int nr = wn + nj2 * 16 + b_n_l;
                    const uint32_t off = (uint32_t)nr * 128
                        + (((uint32_t)(kb + b_kb_l)) ^ (((uint32_t)nr & 7) << 4));
                    LDSM_X4(bh[buf][2*nj2][0], bh[buf][2*nj2][1],
                            bh[buf][2*nj2+1][0], bh[buf][2*nj2+1][1], Bs_h + off);
                    LDSM_X4(bl[buf][2*nj2][0], bl[buf][2*nj2][1],
                            bl[buf][2*nj2+1][0], bl[buf][2*nj2+1][1], Bs_l + off);
                }
            };

            load_frags(0, 0);
            #pragma unroll
            for (int s = 0; s < 4; s++) {
                const int cur = s & 1;
                if (s < 3) load_frags(cur ^ 1, s + 1);
                #pragma unroll
                for (int mi = 0; mi < 4; mi++)
                    #pragma unroll
                    for (int nj = 0; nj < 4; nj++)
                        mma_bf16(acc[mi][nj], ah[cur][mi], bh[cur][nj]);
                #pragma unroll
                for (int mi = 0; mi < 4; mi++)
                    #pragma unroll
                    for (int nj = 0; nj < 4; nj++)
                        mma_bf16(acc[mi][nj], ah[cur][mi], bl[cur][nj]);
                #pragma unroll
                for (int mi = 0; mi < 4; mi++)
                    #pragma unroll
                    for (int nj = 0; nj < 4; nj++)
                        mma_bf16(acc[mi][nj], al[cur][mi], bh[cur][nj]);
            }

            if (++scur == S) scur = 0;
            if (++sld == S) sld = 0;
        }

        // ---------------- epilogue (overlaps next tile's in-flight loads) ----
        const int m0 = tm * 128, n0 = tn * 128;
        const int g  = lane >> 2;
        const int t4 = lane & 3;
        #pragma unroll
        for (int mi = 0; mi < 4; mi++) {
            const int r0 = m0 + wm + mi * 16 + g;
            const int r1 = r0 + 8;
            float rs0 = 1.0f, rs1 = 1.0f;
            if (EPI == 2) { rs0 = rowscale[r0]; rs1 = rowscale[r1]; }
            #pragma unroll
            for (int nj = 0; nj < 4; nj++) {
                const int col = n0 + wn + nj * 8 + t4 * 2;
                float c0 = acc[mi][nj][0], c1 = acc[mi][nj][1];
                float c2 = acc[mi][nj][2], c3 = acc[mi][nj][3];
                if (EPI == 0) {
                    float2 v0; v0.x = c0; v0.y = c1;
                    float2 v1; v1.x = c2; v1.y = c3;
                    *(float2*)(Cf + (size_t)r0 * ldc + col) = v0;
                    *(float2*)(Cf + (size_t)r1 * ldc + col) = v1;
                } else {
                    c0 *= rs0; c1 *= rs0; c2 *= rs1; c3 *= rs1;
                    bf16 h0 = __float2bfloat16(c0), h1 = __float2bfloat16(c1);
                    bf16 h2 = __float2bfloat16(c2), h3 = __float2bfloat16(c3);
                    __nv_bfloat162 hp0; hp0.x = h0; hp0.y = h1;
                    __nv_bfloat162 hp1; hp1.x = h2; hp1.y = h3;
                    __nv_bfloat162 lp0, lp1;
                    lp0.x = __float2bfloat16(c0 - __bfloat162float(h0));
                    lp0.y = __float2bfloat16(c1 - __bfloat162float(h1));
                    lp1.x = __float2bfloat16(c2 - __bfloat162float(h2));
                    lp1.y = __float2bfloat16(c3 - __bfloat162float(h3));
                    *(__nv_bfloat162*)(Chi + (size_t)r0 * ldc + col) = hp0;
                    *(__nv_bfloat162*)(Chi + (size_t)r1 * ldc + col) = hp1;
                    *(__nv_bfloat162*)(Clo + (size_t)r0 * ldc + col) = lp0;
                    *(__nv_bfloat162*)(Clo + (size_t)r1 * ldc + col) = lp1;
                }
            }
        }

        if (!have_next) break;
        tile = ntile; tm = nm; tn = nn;
        ca_h = na_h; ca_l = na_l; cb_h = nb_h; cb_l = nb_l;
    }
}

// ---------------------------------------------------------------------------
// Launch
// ---------------------------------------------------------------------------
static constexpr int GEMM_SMEM = 3 * 4 * 128 * 128;  // 196608 bytes

extern "C" void kernel_launch(void* const* d_in, const int* in_sizes, int n_in,
                              void* d_out, int out_size) {
    const float* x         = (const float*)d_in[0];
    const float* lora_A    = (const float*)d_in[1];
    const float* lora_B    = (const float*)d_in[2];
    const float* magnitude = (const float*)d_in[3];
    const float* direction = (const float*)d_in[4];
    float* out = (float*)d_out;

    bf16 *x_hi, *x_lo, *lB_hi, *lB_lo, *lAT_hi, *lAT_lo, *dir_hi, *dir_lo;
    bf16 *P_hi, *P_lo, *QT_hi, *QT_lo;
    float* cs;
    cudaGetSymbolAddress((void**)&x_hi, g_x_hi);   cudaGetSymbolAddress((void**)&x_lo, g_x_lo);
    cudaGetSymbolAddress((void**)&lB_hi, g_lB_hi); cudaGetSymbolAddress((void**)&lB_lo, g_lB_lo);
    cudaGetSymbolAddress((void**)&lAT_hi, g_lAT_hi); cudaGetSymbolAddress((void**)&lAT_lo, g_lAT_lo);
    cudaGetSymbolAddress((void**)&dir_hi, g_dir_hi); cudaGetSymbolAddress((void**)&dir_lo, g_dir_lo);
    cudaGetSymbolAddress((void**)&P_hi, g_P_hi);   cudaGetSymbolAddress((void**)&P_lo, g_P_lo);
    cudaGetSymbolAddress((void**)&QT_hi, g_QT_hi); cudaGetSymbolAddress((void**)&QT_lo, g_QT_lo);
    cudaGetSymbolAddress((void**)&cs, g_cs);

    cudaFuncSetAttribute(gemm_split<0>, cudaFuncAttributeMaxDynamicSharedMemorySize, GEMM_SMEM);
    cudaFuncSetAttribute(gemm_split<1>, cudaFuncAttributeMaxDynamicSharedMemorySize, GEMM_SMEM);
    cudaFuncSetAttribute(gemm_split<2>, cudaFuncAttributeMaxDynamicSharedMemorySize, GEMM_SMEM);

    int nsm = 148;
    cudaDeviceGetAttribute(&nsm, cudaDevAttrMultiProcessorCount, 0);

    // 1: fused split of x, lora_B, direction
    fused_split<<<BX + 2 * BD, 256>>>(x, lora_B, direction,
                                      x_hi, x_lo, lB_hi, lB_lo, dir_hi, dir_lo);
    // 2: transpose+split lora_A
    dim3 tgrid(DDIM / 32, DDIM / 32), tblk(32, 8);
    transpose_split<<<tgrid, tblk>>>(lora_A, lAT_hi, lAT_lo);
    // 3: fused mag + colscale
    magcol_kernel<<<DDIM, 256>>>(magnitude, direction);

    // 4: P[o,i] = sum_r lora_B[o,r] * lora_A_T[i,r]   (split epilogue)
    gemm_split<1><<<nsm, 256, GEMM_SMEM>>>(lB_hi, lB_lo, lAT_hi, lAT_lo,
                                           nullptr, P_hi, P_lo, nullptr,
                                           DDIM / 128, DDIM / 128);
    // 5: QT[oo,o] = cs[oo] * sum_i direction[oo,i] * P[o,i]  (split + rowscale)
    gemm_split<2><<<nsm, 256, GEMM_SMEM>>>(dir_hi, dir_lo, P_hi, P_lo,
                                           nullptr, QT_hi, QT_lo, cs,
                                           DDIM / 128, DDIM / 128);
    // 6: out[n,oo] = sum_o x[n,o] * QT[oo,o]   (fp32 epilogue)
    gemm_split<0><<<nsm, 256, GEMM_SMEM>>>(x_hi, x_lo, QT_hi, QT_lo,
                                           out, nullptr, nullptr, nullptr,
                                           NTOK / 128, DDIM / 128);
}